// round 17
// baseline (speedup 1.0000x reference)
#include <cuda_runtime.h>
#include <cuda_bf16.h>
#include <stdint.h>

// Problem dims (fixed by dataset): B=64,S=197 -> M=12608 tokens, D=768, H=3072
#define M_TOK 12608
#define M_PAD 12672           // 99 * 128
#define D_DIM 768
#define H_DIM 3072
#define W_ELEMS (D_DIM * H_DIM)   // w1 and w2 have the same element count

// ---------------- scratch (device globals; zero-initialized at load) ----------------
// Vector access allowed ONLY on these aligned globals; harness pointers stay scalar.
__device__ __align__(256) __nv_bfloat16 g_qx [(size_t)M_PAD * D_DIM];   // pad rows stay 0
__device__ __align__(256) __nv_bfloat16 g_qh [(size_t)M_PAD * H_DIM];   // pad rows stay 0
__device__ __align__(256) __nv_bfloat16 g_qw1[(size_t)W_ELEMS];
__device__ __align__(256) __nv_bfloat16 g_qw2[(size_t)W_ELEMS];
__device__ __align__(256) float         g_h  [(size_t)M_TOK * H_DIM];   // fp32 post-GELU hidden
__device__ float         g_sx [M_TOK];
__device__ float         g_sh [M_TOK];
__device__ unsigned      g_hmax[M_TOK];           // row amax of gelu(h); zeroed by quant_x
__device__ unsigned      g_wamax[2];              // zero-init; atomicMax idempotent

// ---------------- helpers ----------------
__device__ __forceinline__ float warpMax(float v) {
#pragma unroll
    for (int o = 16; o > 0; o >>= 1) v = fmaxf(v, __shfl_xor_sync(0xffffffffu, v, o));
    return v;
}

__device__ __forceinline__ float gelu_exact(float v) {
    return 0.5f * v * (1.0f + erff(v * 0.7071067811865475f));
}

__device__ __forceinline__ void cp16(void* sm, const void* gm) {
    unsigned a = (unsigned)__cvta_generic_to_shared(sm);
    asm volatile("cp.async.cg.shared.global [%0], [%1], 16;" :: "r"(a), "l"(gm));
}

__device__ __forceinline__ uint32_t s2u(const void* p) {
    return (uint32_t)__cvta_generic_to_shared(p);
}

// ---------------- elementwise kernels ----------------
// fused: first half of grid handles w1/slot0, second half w2/slot1
__global__ void wamax_both_kernel(const float* __restrict__ w1,
                                  const float* __restrict__ w2, int n) {
    const int half = gridDim.x / 2;
    const int slot = (blockIdx.x >= half) ? 1 : 0;
    const float* w = slot ? w2 : w1;
    const int b = slot ? (blockIdx.x - half) : blockIdx.x;
    float m = 0.f;
    for (int i = b * blockDim.x + threadIdx.x; i < n; i += half * blockDim.x)
        m = fmaxf(m, fabsf(w[i]));                 // scalar harness reads
    __shared__ float sh[8];
    int lane = threadIdx.x & 31, wid = threadIdx.x >> 5;
    m = warpMax(m);
    if (lane == 0) sh[wid] = m;
    __syncthreads();
    if (threadIdx.x == 0) {
        float t = sh[0];
#pragma unroll
        for (int i = 1; i < 8; i++) t = fmaxf(t, sh[i]);
        atomicMax(&g_wamax[slot], __float_as_uint(t));
    }
}

__global__ void quant_w_both_kernel(const float* __restrict__ w1,
                                    const float* __restrict__ w2, int n2) {
    const int half = gridDim.x / 2;
    const int slot = (blockIdx.x >= half) ? 1 : 0;
    const float* w = slot ? w2 : w1;
    __nv_bfloat162* q2 = (__nv_bfloat162*)(slot ? g_qw2 : g_qw1);  // mine: 4B stores OK
    const int b = slot ? (blockIdx.x - half) : blockIdx.x;
    const float s = fmaxf(__uint_as_float(g_wamax[slot]), 1e-6f) / 127.0f;
    for (int i = b * blockDim.x + threadIdx.x; i < n2; i += half * blockDim.x) {
        float a = w[2 * i], bb = w[2 * i + 1];     // scalar harness reads
        __nv_bfloat162 v;
        v.x = __float2bfloat16(rintf(a / s));
        v.y = __float2bfloat16(rintf(bb / s));
        q2[i] = v;
    }
}

__global__ void quant_x_kernel(const float* __restrict__ x) {
    int row = blockIdx.x;
    if (threadIdx.x == 0) g_hmax[row] = 0u;        // reset fused-amax accumulator each run
    const float* xr = x + (size_t)row * D_DIM;
    float m = 0.f;
    for (int i = threadIdx.x; i < D_DIM; i += 256) m = fmaxf(m, fabsf(xr[i]));  // scalar
    __shared__ float sh[8];
    __shared__ float s_bcast;
    int lane = threadIdx.x & 31, wid = threadIdx.x >> 5;
    m = warpMax(m);
    if (lane == 0) sh[wid] = m;
    __syncthreads();
    if (threadIdx.x == 0) {
        float t = sh[0];
#pragma unroll
        for (int i = 1; i < 8; i++) t = fmaxf(t, sh[i]);
        float s = fmaxf(t, 1e-6f) / 127.0f;
        s_bcast = s;
        g_sx[row] = s;
    }
    __syncthreads();
    float s = s_bcast;
    __nv_bfloat162* q2 = (__nv_bfloat162*)(g_qx + (size_t)row * D_DIM);   // mine
    for (int i = threadIdx.x; i < D_DIM / 2; i += 256) {
        float a = xr[2 * i], b = xr[2 * i + 1];    // scalar harness reads
        __nv_bfloat162 v;
        v.x = __float2bfloat16(rintf(a / s));
        v.y = __float2bfloat16(rintf(b / s));
        q2[i] = v;
    }
}

// single-pass: amax already accumulated by gemm1 epilogue into g_hmax
__global__ void quant_h_kernel() {
    int row = blockIdx.x;
    float s = fmaxf(__uint_as_float(g_hmax[row]), 1e-6f) / 127.0f;
    if (threadIdx.x == 0) g_sh[row] = s;
    const float4* hr4 = (const float4*)(g_h + (size_t)row * H_DIM);       // mine: float4 OK
    uint2* q4 = (uint2*)(g_qh + (size_t)row * H_DIM);                     // mine: 8B stores OK
    for (int i = threadIdx.x; i < H_DIM / 4; i += 256) {
        float4 v = hr4[i];
        __nv_bfloat162 lo, hi;
        lo.x = __float2bfloat16(rintf(v.x / s));
        lo.y = __float2bfloat16(rintf(v.y / s));
        hi.x = __float2bfloat16(rintf(v.z / s));
        hi.y = __float2bfloat16(rintf(v.w / s));
        uint2 o;
        o.x = *(uint32_t*)&lo;
        o.y = *(uint32_t*)&hi;
        q4[i] = o;
    }
}

// ---------------- GEMM: C[M,N] = A[M,K] @ B[N,K]^T, bf16 in, fp32 acc ----------------
// NEW geometry: block 128x128x64, 4 warps (2x2), warp tile 64x64, 128 threads,
// 2 CTAs/SM (regs <=256, smem 110.6KB/CTA). Crossbar bytes per MMA halved vs 64x32;
// two independent barrier domains per SM. ldmatrix x4 loads, 3-stage cp.async,
// one __syncthreads per k-tile, fused amax epilogue (all R16-proven pieces).
#define BM 128
#define BN 128
#define BK 64
#define SK 72                   // row stride 144B: conflict-free ldmatrix phases
#define STAGE_B (2 * BM * SK * 2)     // 36864 B
#define GSMEM   (3 * STAGE_B)         // 110592 B
#define NTHR 128

template <bool GELU, int PHASE>
__global__ void __launch_bounds__(NTHR, 2) gemm_kernel(const float* __restrict__ bias,
                                                       float* __restrict__ Cout, int M) {
    const int N = (PHASE == 0) ? H_DIM : D_DIM;
    const int K = (PHASE == 0) ? D_DIM : H_DIM;
    const __nv_bfloat16* __restrict__ A = (PHASE == 0) ? g_qx : g_qh;
    const __nv_bfloat16* __restrict__ B = (PHASE == 0) ? g_qw1 : g_qw2;
    const float* __restrict__ rowscale  = (PHASE == 0) ? g_sx : g_sh;
    float* __restrict__ C               = (PHASE == 0) ? g_h : Cout;

    extern __shared__ __align__(128) char dsm[];

    const int tid  = threadIdx.x;
    const int lane = tid & 31, warp = tid >> 5;
    const int wm = warp & 1, wn = warp >> 1;   // 2 warps in M, 2 in N
    const int bm = blockIdx.y * BM, bn = blockIdx.x * BN;

    float acc[4][8][4];
#pragma unroll
    for (int i = 0; i < 4; i++)
#pragma unroll
        for (int j = 0; j < 8; j++)
#pragma unroll
            for (int r = 0; r < 4; r++) acc[i][j][r] = 0.f;

    auto tileA = [&](int st) { return (__nv_bfloat16*)(dsm + st * STAGE_B); };
    auto tileB = [&](int st) { return (__nv_bfloat16*)(dsm + st * STAGE_B + BM * SK * 2); };

    auto load_stage = [&](int st, int k0) {
        __nv_bfloat16* sA = tileA(st);
        __nv_bfloat16* sB = tileB(st);
#pragma unroll
        for (int j = 0; j < 16; j++) {               // 2048 chunks of 16B / 128 thr
            int idx = tid + j * NTHR;
            int r = (idx >> 3) & 127, c = idx & 7;
            bool isA = idx < 1024;
            const __nv_bfloat16* src = (isA ? A + (size_t)(bm + r) * K
                                            : B + (size_t)(bn + r) * K) + k0 + c * 8;
            __nv_bfloat16* dst = (isA ? sA : sB) + r * SK + c * 8;
            cp16(dst, src);
        }
        asm volatile("cp.async.commit_group;");
    };

    const int ktiles = K / BK;
    load_stage(0, 0);
    load_stage(1, BK);

    const int lrow = lane >> 2;
    const int lcol = (lane & 3) << 1;
    // A ldmatrix.x4 per-lane offset (rows 0-15, +16B half-column)
    const uint32_t a_lane = (uint32_t)((lane & 15) * (SK * 2) + (lane >> 4) * 16);
    // B ldmatrix.x4 paired per-lane offset (m0/m1 = rows+col halves, m2/m3 = +8 rows)
    const uint32_t b4_lane = (uint32_t)((lane & 7) * (SK * 2) + ((lane >> 3) & 1) * 16
                                        + (lane >> 4) * 8 * (SK * 2));

    for (int kt = 0; kt < ktiles; ++kt) {
        asm volatile("cp.async.wait_group 1;" ::: "memory");
        __syncthreads();

        if (kt + 2 < ktiles) load_stage((kt + 2) % 3, (kt + 2) * BK);
        else asm volatile("cp.async.commit_group;");

        const int st = kt % 3;
        const uint32_t saddr = s2u(tileA(st));
        const uint32_t baddr = s2u(tileB(st));

#pragma unroll
        for (int kk = 0; kk < BK; kk += 16) {
            uint32_t af[4][4], bf[8][2];
#pragma unroll
            for (int mi = 0; mi < 4; mi++) {
                uint32_t addr = saddr + (uint32_t)((wm * 64 + mi * 16) * (SK * 2) + kk * 2)
                                      + a_lane;
                asm volatile("ldmatrix.sync.aligned.m8n8.x4.shared.b16 {%0,%1,%2,%3}, [%4];"
                             : "=r"(af[mi][0]), "=r"(af[mi][1]),
                               "=r"(af[mi][2]), "=r"(af[mi][3])
                             : "r"(addr));
            }
#pragma unroll
            for (int nj = 0; nj < 4; nj++) {         // pairs (2nj, 2nj+1) in one x4
                uint32_t addr = baddr + (uint32_t)((wn * 64 + nj * 16) * (SK * 2) + kk * 2)
                                      + b4_lane;
                asm volatile("ldmatrix.sync.aligned.m8n8.x4.shared.b16 {%0,%1,%2,%3}, [%4];"
                             : "=r"(bf[2 * nj][0]), "=r"(bf[2 * nj][1]),
                               "=r"(bf[2 * nj + 1][0]), "=r"(bf[2 * nj + 1][1])
                             : "r"(addr));
            }
#pragma unroll
            for (int mi = 0; mi < 4; mi++)
#pragma unroll
                for (int ni = 0; ni < 8; ni++) {
                    asm volatile(
                        "mma.sync.aligned.m16n8k16.row.col.f32.bf16.bf16.f32 "
                        "{%0,%1,%2,%3}, {%4,%5,%6,%7}, {%8,%9}, {%0,%1,%2,%3};"
                        : "+f"(acc[mi][ni][0]), "+f"(acc[mi][ni][1]),
                          "+f"(acc[mi][ni][2]), "+f"(acc[mi][ni][3])
                        : "r"(af[mi][0]), "r"(af[mi][1]), "r"(af[mi][2]), "r"(af[mi][3]),
                          "r"(bf[ni][0]), "r"(bf[ni][1]));
                }
        }
    }
    asm volatile("cp.async.wait_group 0;" ::: "memory");

    // epilogue: (acc + bias) * (rowscale * sw)  [+ exact GELU + fused row-amax]
    const float sw = fmaxf(__uint_as_float(g_wamax[PHASE]), 1e-6f) / 127.0f;
#pragma unroll
    for (int mi = 0; mi < 4; mi++) {
#pragma unroll
        for (int h = 0; h < 2; h++) {
            int row = bm + wm * 64 + mi * 16 + lrow + h * 8;
            const bool ok = (row < M);
            float rs = ok ? rowscale[row] * sw : 0.f;
            float vv[8][2];
            float lm = 0.f;
#pragma unroll
            for (int ni = 0; ni < 8; ni++) {
                int col = bn + wn * 64 + ni * 8 + lcol;
                float v0 = (acc[mi][ni][h * 2 + 0] + bias[col    ]) * rs;
                float v1 = (acc[mi][ni][h * 2 + 1] + bias[col + 1]) * rs;
                if (GELU) {
                    v0 = gelu_exact(v0);
                    v1 = gelu_exact(v1);
                    lm = fmaxf(lm, fmaxf(fabsf(v0), fabsf(v1)));
                }
                vv[ni][0] = v0;
                vv[ni][1] = v1;
            }
            if (GELU) {   // quad-level reduce (lanes 4k..4k+3 share row), full-mask shfl
                lm = fmaxf(lm, __shfl_xor_sync(0xffffffffu, lm, 1));
                lm = fmaxf(lm, __shfl_xor_sync(0xffffffffu, lm, 2));
                if (ok && (lane & 3) == 0) atomicMax(&g_hmax[row], __float_as_uint(lm));
            }
            if (ok) {
#pragma unroll
                for (int ni = 0; ni < 8; ni++) {
                    int col = bn + wn * 64 + ni * 8 + lcol;
                    if (PHASE == 0) {
                        float2 o = {vv[ni][0], vv[ni][1]};
                        *(float2*)(C + (size_t)row * N + col) = o;   // g_h: mine
                    } else {
                        C[(size_t)row * N + col    ] = vv[ni][0];    // d_out: scalar
                        C[(size_t)row * N + col + 1] = vv[ni][1];
                    }
                }
            }
        }
    }
}

// ---------------- launch ----------------
// ncu -s 5 has a +2 harness-launch offset -> profiles MY index 3 (gemm1).
extern "C" void kernel_launch(void* const* d_in, const int* in_sizes, int n_in,
                              void* d_out, int out_size) {
    const float* x  = (const float*)d_in[0];
    const float* w1 = (const float*)d_in[1];
    const float* b1 = (const float*)d_in[2];
    const float* w2 = (const float*)d_in[3];
    const float* b2 = (const float*)d_in[4];
    const int M = in_sizes[0] / D_DIM;   // 12608

    cudaFuncSetAttribute(gemm_kernel<true, 0>,
                         cudaFuncAttributeMaxDynamicSharedMemorySize, GSMEM);
    cudaFuncSetAttribute(gemm_kernel<false, 1>,
                         cudaFuncAttributeMaxDynamicSharedMemorySize, GSMEM);

    wamax_both_kernel<<<2048, 256>>>(w1, w2, W_ELEMS);            // 0
    quant_w_both_kernel<<<4096, 256>>>(w1, w2, W_ELEMS / 2);      // 1
    quant_x_kernel<<<M, 256>>>(x);                                // 2 (also zeroes g_hmax)

    dim3 g1(H_DIM / BN, (M + BM - 1) / BM);
    gemm_kernel<true, 0><<<g1, NTHR, GSMEM>>>(b1, nullptr, M);    // 3  <- ncu target

    quant_h_kernel<<<M, 256>>>();                                 // 4 (single pass)

    dim3 g2(D_DIM / BN, (M + BM - 1) / BM);
    gemm_kernel<false, 1><<<g2, NTHR, GSMEM>>>(b2, (float*)d_out, M);  // 5
}